// round 2
// baseline (speedup 1.0000x reference)
#include <cuda_runtime.h>

// Problem constants
constexpr int B  = 4;
constexpr int L  = 2048;
constexpr int D  = 1024;
constexpr int H  = 16;
constexpr int HD = 64;
constexpr int M  = B * L;          // 8192 rows
constexpr float SCALE = 0.125f;    // 1/sqrt(64)

// Scratch buffers (allocation-free rule: __device__ globals)
__device__ float g_Q[(size_t)M * D];
__device__ float g_K[(size_t)M * D];
__device__ float g_V[(size_t)M * D];
__device__ float g_att[(size_t)M * D];

// ---------------------------------------------------------------------------
// SGEMM (NT):  C[M,N] = A[M,K] * W[N,K]^T + bias[N]
// BM=BN=128, BK=8, 256 threads, 8x8 micro-tile per thread.
// A, W row-major. Hardcoded K = N = D = 1024.
// ---------------------------------------------------------------------------
__global__ __launch_bounds__(256) void sgemm_nt_bias(
    const float* __restrict__ A, const float* __restrict__ W,
    const float* __restrict__ bias, float* __restrict__ C)
{
    constexpr int K = D;
    constexpr int N = D;

    __shared__ float As[8][128];
    __shared__ float Ws[8][128];

    const int t  = threadIdx.x;
    const int tx = t & 15;         // 0..15
    const int ty = t >> 4;         // 0..15
    const int rowBase = blockIdx.y * 128;
    const int colBase = blockIdx.x * 128;

    // load mapping: each thread loads one float4 of A and one of W per k-tile
    const int lr = t >> 1;         // 0..127 (tile row)
    const int lc = (t & 1) * 4;    // 0 or 4 (k offset)
    const float* Aptr = A + (size_t)(rowBase + lr) * K + lc;
    const float* Wptr = W + (size_t)(colBase + lr) * K + lc;

    float acc[8][8] = {};

    for (int kt = 0; kt < K; kt += 8) {
        float4 a = *(const float4*)(Aptr + kt);
        float4 w = *(const float4*)(Wptr + kt);
        As[lc + 0][lr] = a.x; As[lc + 1][lr] = a.y;
        As[lc + 2][lr] = a.z; As[lc + 3][lr] = a.w;
        Ws[lc + 0][lr] = w.x; Ws[lc + 1][lr] = w.y;
        Ws[lc + 2][lr] = w.z; Ws[lc + 3][lr] = w.w;
        __syncthreads();

        #pragma unroll
        for (int k = 0; k < 8; k++) {
            float ra[8], rb[8];
            *(float4*)&ra[0] = *(const float4*)&As[k][ty * 8 + 0];
            *(float4*)&ra[4] = *(const float4*)&As[k][ty * 8 + 4];
            *(float4*)&rb[0] = *(const float4*)&Ws[k][tx * 8 + 0];
            *(float4*)&rb[4] = *(const float4*)&Ws[k][tx * 8 + 4];
            #pragma unroll
            for (int i = 0; i < 8; i++)
                #pragma unroll
                for (int j = 0; j < 8; j++)
                    acc[i][j] += ra[i] * rb[j];
        }
        __syncthreads();
    }

    // epilogue: add bias, store
    #pragma unroll
    for (int i = 0; i < 8; i++) {
        const int row = rowBase + ty * 8 + i;
        #pragma unroll
        for (int j = 0; j < 8; j += 4) {
            const int col = colBase + tx * 8 + j;
            float4 o;
            o.x = acc[i][j + 0] + bias[col + 0];
            o.y = acc[i][j + 1] + bias[col + 1];
            o.z = acc[i][j + 2] + bias[col + 2];
            o.w = acc[i][j + 3] + bias[col + 3];
            *(float4*)&C[(size_t)row * N + col] = o;
        }
    }
}

// ---------------------------------------------------------------------------
// Flash attention (fp32). One thread = one query row. 128 queries / block.
// K/V streamed through SMEM in 64-key tiles. Per-key online softmax:
// the max-rescale branch fires ~log(L) times per row (rare divergence).
// grid: (L/128, H, B)
// ---------------------------------------------------------------------------
__global__ __launch_bounds__(128) void attention_kernel(float* __restrict__ out)
{
    __shared__ float Ks[64][64];
    __shared__ float Vs[64][64];

    const int tid = threadIdx.x;
    const int h = blockIdx.y;
    const int b = blockIdx.z;
    const int q = blockIdx.x * 128 + tid;

    // Q row into registers, pre-scaled
    const float* Qrow = g_Q + ((size_t)(b * L + q)) * D + h * HD;
    float Qr[64];
    #pragma unroll
    for (int d = 0; d < 64; d += 4) {
        float4 v = *(const float4*)&Qrow[d];
        Qr[d + 0] = v.x * SCALE; Qr[d + 1] = v.y * SCALE;
        Qr[d + 2] = v.z * SCALE; Qr[d + 3] = v.w * SCALE;
    }

    float O[64] = {};
    float m = -1e30f;
    float l = 0.0f;

    for (int kt = 0; kt < L; kt += 64) {
        const float* Kbase = g_K + ((size_t)(b * L + kt)) * D + h * HD;
        const float* Vbase = g_V + ((size_t)(b * L + kt)) * D + h * HD;
        __syncthreads();
        // cooperative tile load: 64 rows x 16 float4 per matrix
        #pragma unroll
        for (int i = tid; i < 64 * 16; i += 128) {
            const int r = i >> 4;
            const int c = (i & 15) << 2;
            *(float4*)&Ks[r][c] = *(const float4*)&Kbase[(size_t)r * D + c];
            *(float4*)&Vs[r][c] = *(const float4*)&Vbase[(size_t)r * D + c];
        }
        __syncthreads();

        for (int j = 0; j < 64; j++) {
            // s = <Q, K_j> with 4 independent accumulator chains
            float s0 = 0.f, s1 = 0.f, s2 = 0.f, s3 = 0.f;
            #pragma unroll
            for (int d = 0; d < 64; d += 4) {
                float4 kv = *(const float4*)&Ks[j][d];
                s0 += Qr[d + 0] * kv.x;
                s1 += Qr[d + 1] * kv.y;
                s2 += Qr[d + 2] * kv.z;
                s3 += Qr[d + 3] * kv.w;
            }
            const float s = (s0 + s1) + (s2 + s3);

            if (s > m) {            // rare: rescale running state
                const float corr = __expf(m - s);
                m = s;
                l *= corr;
                #pragma unroll
                for (int d = 0; d < 64; d++) O[d] *= corr;
            }
            const float p = __expf(s - m);
            l += p;
            #pragma unroll
            for (int d = 0; d < 64; d += 4) {
                float4 vv = *(const float4*)&Vs[j][d];
                O[d + 0] += p * vv.x;
                O[d + 1] += p * vv.y;
                O[d + 2] += p * vv.z;
                O[d + 3] += p * vv.w;
            }
        }
    }

    const float inv = 1.0f / l;
    float* outp = out + ((size_t)(b * L + q)) * D + h * HD;
    #pragma unroll
    for (int d = 0; d < 64; d += 4) {
        float4 o;
        o.x = O[d + 0] * inv; o.y = O[d + 1] * inv;
        o.z = O[d + 2] * inv; o.w = O[d + 3] * inv;
        *(float4*)&outp[d] = o;
    }
}

// ---------------------------------------------------------------------------
// Launch
// Inputs (metadata order): q, k, v, Wq, bq, Wk, bk, Wv, bv, Wo, bo
// ---------------------------------------------------------------------------
extern "C" void kernel_launch(void* const* d_in, const int* in_sizes, int n_in,
                              void* d_out, int out_size)
{
    (void)in_sizes; (void)n_in; (void)out_size;
    const float* q  = (const float*)d_in[0];
    const float* k  = (const float*)d_in[1];
    const float* v  = (const float*)d_in[2];
    const float* Wq = (const float*)d_in[3];
    const float* bq = (const float*)d_in[4];
    const float* Wk = (const float*)d_in[5];
    const float* bk = (const float*)d_in[6];
    const float* Wv = (const float*)d_in[7];
    const float* bv = (const float*)d_in[8];
    const float* Wo = (const float*)d_in[9];
    const float* bo = (const float*)d_in[10];
    float* out = (float*)d_out;

    float *Qp, *Kp, *Vp, *Ap;
    cudaGetSymbolAddress((void**)&Qp, g_Q);
    cudaGetSymbolAddress((void**)&Kp, g_K);
    cudaGetSymbolAddress((void**)&Vp, g_V);
    cudaGetSymbolAddress((void**)&Ap, g_att);

    const dim3 gemmGrid(D / 128, M / 128);   // (8, 64)
    sgemm_nt_bias<<<gemmGrid, 256>>>(q, Wq, bq, Qp);
    sgemm_nt_bias<<<gemmGrid, 256>>>(k, Wk, bk, Kp);
    sgemm_nt_bias<<<gemmGrid, 256>>>(v, Wv, bv, Vp);

    const dim3 attGrid(L / 128, H, B);       // (16, 16, 4)
    attention_kernel<<<attGrid, 128>>>(Ap);

    sgemm_nt_bias<<<gemmGrid, 256>>>(Ap, Wo, bo, out);
}

// round 4
// speedup vs baseline: 3.0534x; 3.0534x over previous
#include <cuda_runtime.h>

// Problem constants
constexpr int B_  = 4;
constexpr int L_  = 2048;
constexpr int D_  = 1024;
constexpr int H_  = 16;
constexpr int HD_ = 64;
constexpr int M_  = B_ * L_;          // 8192 rows
constexpr float SCALE = 0.125f;       // 1/sqrt(64)

// Scratch (allocation-free rule: __device__ globals)
__device__ float g_Q[(size_t)M_ * D_];
__device__ float g_K[(size_t)M_ * D_];
__device__ float g_V[(size_t)M_ * D_];
__device__ float g_att[(size_t)M_ * D_];

// ---------------------------------------------------------------------------
// tf32 helpers
// ---------------------------------------------------------------------------
__device__ __forceinline__ float f2tf(float f) {
    unsigned u;
    asm("cvt.rna.tf32.f32 %0, %1;" : "=r"(u) : "f"(f));
    return __uint_as_float(u);
}

// D = A(16x8, row) * B(8x8, col) + D,  tf32 inputs, fp32 accum
__device__ __forceinline__ void mma8(float* c, const unsigned* a, const unsigned* b) {
    asm volatile(
        "mma.sync.aligned.m16n8k8.row.col.f32.tf32.tf32.f32 "
        "{%0,%1,%2,%3}, {%4,%5,%6,%7}, {%8,%9}, {%0,%1,%2,%3};"
        : "+f"(c[0]), "+f"(c[1]), "+f"(c[2]), "+f"(c[3])
        : "r"(a[0]), "r"(a[1]), "r"(a[2]), "r"(a[3]), "r"(b[0]), "r"(b[1]));
}

// ---------------------------------------------------------------------------
// tf32 GEMM (NT): C[M,1024] = A[M,1024] * W[1024,1024]^T + bias
// 128x128 block, BK=16, 256 threads, 8 warps as 2(M)x4(N) -> 64x32 warp tile.
// Register-prefetch double buffering. K = N = 1024 hardcoded.
// ---------------------------------------------------------------------------
constexpr int KPAD = 20;   // (20*m + k) mod 32 hits all 32 banks for frag loads

__global__ __launch_bounds__(256) void gemm_tf32(
    const float* __restrict__ A, const float* __restrict__ W,
    const float* __restrict__ bias, float* __restrict__ C)
{
    __shared__ float As[128][KPAD];
    __shared__ float Ws[128][KPAD];

    const int t    = threadIdx.x;
    const int lane = t & 31;
    const int gid  = lane >> 2;      // 0..7
    const int tig  = lane & 3;       // 0..3
    const int wid  = t >> 5;
    const int wm   = wid & 1;        // 2 warps in M (64 rows each)
    const int wn   = wid >> 1;       // 4 warps in N (32 cols each)
    const int rowB = blockIdx.y * 128;
    const int colB = blockIdx.x * 128;

    // staging map: thread covers rows sr and sr+64, k-offset sc..sc+3
    const int sr = t >> 2;           // 0..63
    const int sc = (t & 3) * 4;      // 0,4,8,12
    const float* Ag = A + (size_t)(rowB + sr) * D_ + sc;
    const float* Wg = W + (size_t)(colB + sr) * D_ + sc;

    float acc[4][4][4] = {};         // [Mtile][Ntile][frag]

    float4 pa0 = *(const float4*)Ag;
    float4 pa1 = *(const float4*)(Ag + (size_t)64 * D_);
    float4 pw0 = *(const float4*)Wg;
    float4 pw1 = *(const float4*)(Wg + (size_t)64 * D_);

#define STASH()                                                                \
    do {                                                                       \
        As[sr][sc+0]=f2tf(pa0.x); As[sr][sc+1]=f2tf(pa0.y);                    \
        As[sr][sc+2]=f2tf(pa0.z); As[sr][sc+3]=f2tf(pa0.w);                    \
        As[sr+64][sc+0]=f2tf(pa1.x); As[sr+64][sc+1]=f2tf(pa1.y);              \
        As[sr+64][sc+2]=f2tf(pa1.z); As[sr+64][sc+3]=f2tf(pa1.w);              \
        Ws[sr][sc+0]=f2tf(pw0.x); Ws[sr][sc+1]=f2tf(pw0.y);                    \
        Ws[sr][sc+2]=f2tf(pw0.z); Ws[sr][sc+3]=f2tf(pw0.w);                    \
        Ws[sr+64][sc+0]=f2tf(pw1.x); Ws[sr+64][sc+1]=f2tf(pw1.y);              \
        Ws[sr+64][sc+2]=f2tf(pw1.z); Ws[sr+64][sc+3]=f2tf(pw1.w);              \
    } while (0)

    STASH();
    __syncthreads();

    for (int kt = 0; kt < 64; kt++) {
        if (kt < 63) {
            const int ko = (kt + 1) * 16;
            pa0 = *(const float4*)(Ag + ko);
            pa1 = *(const float4*)(Ag + (size_t)64 * D_ + ko);
            pw0 = *(const float4*)(Wg + ko);
            pw1 = *(const float4*)(Wg + (size_t)64 * D_ + ko);
        }
        #pragma unroll
        for (int kc = 0; kc < 2; kc++) {
            const int kk = kc * 8;
            unsigned af[4][4], bf[4][2];
            #pragma unroll
            for (int i = 0; i < 4; i++) {
                const int r = wm * 64 + i * 16 + gid;
                af[i][0] = __float_as_uint(As[r    ][kk + tig    ]);
                af[i][1] = __float_as_uint(As[r + 8][kk + tig    ]);
                af[i][2] = __float_as_uint(As[r    ][kk + tig + 4]);
                af[i][3] = __float_as_uint(As[r + 8][kk + tig + 4]);
            }
            #pragma unroll
            for (int j = 0; j < 4; j++) {
                const int cc = wn * 32 + j * 8 + gid;
                bf[j][0] = __float_as_uint(Ws[cc][kk + tig    ]);
                bf[j][1] = __float_as_uint(Ws[cc][kk + tig + 4]);
            }
            #pragma unroll
            for (int i = 0; i < 4; i++)
                #pragma unroll
                for (int j = 0; j < 4; j++)
                    mma8(acc[i][j], af[i], bf[j]);
        }
        __syncthreads();
        if (kt < 63) {
            STASH();
            __syncthreads();
        }
    }
#undef STASH

    // epilogue: bias + store (c0,c1 are adjacent cols -> float2)
    #pragma unroll
    for (int i = 0; i < 4; i++) {
        const int row = rowB + wm * 64 + i * 16 + gid;
        #pragma unroll
        for (int j = 0; j < 4; j++) {
            const int col = colB + wn * 32 + j * 8 + 2 * tig;
            const float bx = bias[col], by = bias[col + 1];
            float2 v0 = make_float2(acc[i][j][0] + bx, acc[i][j][1] + by);
            float2 v1 = make_float2(acc[i][j][2] + bx, acc[i][j][3] + by);
            *(float2*)&C[(size_t)row * D_ + col]       = v0;
            *(float2*)&C[(size_t)(row + 8) * D_ + col] = v1;
        }
    }
}

// ---------------------------------------------------------------------------
// Flash attention, tf32 tensor cores.
// Q tile 128 rows, key tile 64. 8 warps as 4(M)x2(N): 32x32 warp tiles.
// S -> smem -> softmax (2 threads/row) -> P(tf32) x V accumulate.
// Dynamic smem ~104KB. grid (L/128, H, B), 256 threads.
// ---------------------------------------------------------------------------
// smem float offsets
constexpr int QS_OFF = 0;              // [128][68]
constexpr int KS_OFF = 8704;           // [64][68]
constexpr int VS_OFF = 13056;          // [64][72]
constexpr int PS_OFF = 17664;          // [128][68]
constexpr int CO_OFF = 26368;          // corr[128]
constexpr int LI_OFF = 26496;          // inv_l[128]
constexpr int ATT_SMEM_BYTES = 26624 * 4;

__global__ __launch_bounds__(256) void attn_tf32(float* __restrict__ out)
{
    extern __shared__ float sm[];
    float (*Qs)[68] = (float(*)[68])(sm + QS_OFF);
    float (*Ks)[68] = (float(*)[68])(sm + KS_OFF);
    float (*Vs)[72] = (float(*)[72])(sm + VS_OFF);
    float (*Ps)[68] = (float(*)[68])(sm + PS_OFF);
    float* corr_s = sm + CO_OFF;
    float* linv_s = sm + LI_OFF;

    const int t    = threadIdx.x;
    const int lane = t & 31;
    const int gid  = lane >> 2;
    const int tig  = lane & 3;
    const int wid  = t >> 5;
    const int wm   = wid & 3;          // 4 warps in M: 32-row strips
    const int wn   = wid >> 2;         // 2 warps in N: 32-col strips
    const int b    = blockIdx.z;
    const int h    = blockIdx.y;
    const int qB   = blockIdx.x * 128;

    // stage Q tile (pre-scaled, tf32-rounded)
    {
        const float* Qg = g_Q + ((size_t)(b * L_ + qB)) * D_ + h * HD_;
        for (int i = t; i < 128 * 16; i += 256) {
            const int r = i >> 4, c = (i & 15) * 4;
            float4 v = *(const float4*)&Qg[(size_t)r * D_ + c];
            Qs[r][c + 0] = f2tf(v.x * SCALE);
            Qs[r][c + 1] = f2tf(v.y * SCALE);
            Qs[r][c + 2] = f2tf(v.z * SCALE);
            Qs[r][c + 3] = f2tf(v.w * SCALE);
        }
    }

    // softmax row ownership: 2 threads per row
    const int srow = t >> 1;
    const int scol = (t & 1) * 32;
    float mrow = -1e30f, lrow = 0.0f;

    float Oacc[2][4][4] = {};          // [Mtile][Ntile(HD)][frag]

    for (int kt = 0; kt < L_; kt += 64) {
        const float* Kg = g_K + ((size_t)(b * L_ + kt)) * D_ + h * HD_;
        const float* Vg = g_V + ((size_t)(b * L_ + kt)) * D_ + h * HD_;
        __syncthreads();               // previous iter done with Ks/Vs
        for (int i = t; i < 64 * 16; i += 256) {
            const int r = i >> 4, c = (i & 15) * 4;
            float4 kv = *(const float4*)&Kg[(size_t)r * D_ + c];
            float4 vv = *(const float4*)&Vg[(size_t)r * D_ + c];
            Ks[r][c + 0] = f2tf(kv.x); Ks[r][c + 1] = f2tf(kv.y);
            Ks[r][c + 2] = f2tf(kv.z); Ks[r][c + 3] = f2tf(kv.w);
            Vs[r][c + 0] = f2tf(vv.x); Vs[r][c + 1] = f2tf(vv.y);
            Vs[r][c + 2] = f2tf(vv.z); Vs[r][c + 3] = f2tf(vv.w);
        }
        __syncthreads();

        // S = Qs . Ks^T   (128x64, this warp: 32x32)
        float Sacc[2][4][4] = {};
        #pragma unroll
        for (int kc = 0; kc < 8; kc++) {
            const int kk = kc * 8;
            unsigned af[2][4], bf[4][2];
            #pragma unroll
            for (int i = 0; i < 2; i++) {
                const int r = wm * 32 + i * 16 + gid;
                af[i][0] = __float_as_uint(Qs[r    ][kk + tig    ]);
                af[i][1] = __float_as_uint(Qs[r + 8][kk + tig    ]);
                af[i][2] = __float_as_uint(Qs[r    ][kk + tig + 4]);
                af[i][3] = __float_as_uint(Qs[r + 8][kk + tig + 4]);
            }
            #pragma unroll
            for (int j = 0; j < 4; j++) {
                const int key = wn * 32 + j * 8 + gid;
                bf[j][0] = __float_as_uint(Ks[key][kk + tig    ]);
                bf[j][1] = __float_as_uint(Ks[key][kk + tig + 4]);
            }
            #pragma unroll
            for (int i = 0; i < 2; i++)
                #pragma unroll
                for (int j = 0; j < 4; j++)
                    mma8(Sacc[i][j], af[i], bf[j]);
        }
        // spill S to smem
        #pragma unroll
        for (int i = 0; i < 2; i++) {
            const int r = wm * 32 + i * 16 + gid;
            #pragma unroll
            for (int j = 0; j < 4; j++) {
                const int c = wn * 32 + j * 8 + 2 * tig;
                Ps[r    ][c] = Sacc[i][j][0]; Ps[r    ][c + 1] = Sacc[i][j][1];
                Ps[r + 8][c] = Sacc[i][j][2]; Ps[r + 8][c + 1] = Sacc[i][j][3];
            }
        }
        __syncthreads();

        // online softmax on rows (2 threads/row, 32 cols each)
        {
            float mx = -1e30f;
            #pragma unroll 8
            for (int c = 0; c < 32; c++) mx = fmaxf(mx, Ps[srow][scol + c]);
            mx = fmaxf(mx, __shfl_xor_sync(0xffffffffu, mx, 1));
            const float mnew = fmaxf(mrow, mx);
            const float corr = __expf(mrow - mnew);
            float sum = 0.0f;
            #pragma unroll 8
            for (int c = 0; c < 32; c++) {
                const float p = __expf(Ps[srow][scol + c] - mnew);
                Ps[srow][scol + c] = f2tf(p);
                sum += p;
            }
            sum += __shfl_xor_sync(0xffffffffu, sum, 1);
            lrow = lrow * corr + sum;
            mrow = mnew;
            if ((t & 1) == 0) corr_s[srow] = corr;
        }
        __syncthreads();

        // rescale O, then O += P . V   (k = 64 keys)
        #pragma unroll
        for (int i = 0; i < 2; i++) {
            const int r = wm * 32 + i * 16 + gid;
            const float c0 = corr_s[r], c1 = corr_s[r + 8];
            #pragma unroll
            for (int j = 0; j < 4; j++) {
                Oacc[i][j][0] *= c0; Oacc[i][j][1] *= c0;
                Oacc[i][j][2] *= c1; Oacc[i][j][3] *= c1;
            }
        }
        #pragma unroll
        for (int kc = 0; kc < 8; kc++) {
            const int kk = kc * 8;
            unsigned af[2][4], bf[4][2];
            #pragma unroll
            for (int i = 0; i < 2; i++) {
                const int r = wm * 32 + i * 16 + gid;
                af[i][0] = __float_as_uint(Ps[r    ][kk + tig    ]);
                af[i][1] = __float_as_uint(Ps[r + 8][kk + tig    ]);
                af[i][2] = __float_as_uint(Ps[r    ][kk + tig + 4]);
                af[i][3] = __float_as_uint(Ps[r + 8][kk + tig + 4]);
            }
            #pragma unroll
            for (int j = 0; j < 4; j++) {
                const int hd = wn * 32 + j * 8 + gid;
                bf[j][0] = __float_as_uint(Vs[kk + tig    ][hd]);
                bf[j][1] = __float_as_uint(Vs[kk + tig + 4][hd]);
            }
            #pragma unroll
            for (int i = 0; i < 2; i++)
                #pragma unroll
                for (int j = 0; j < 4; j++)
                    mma8(Oacc[i][j], af[i], bf[j]);
        }
    }

    // final normalization factors
    if ((t & 1) == 0) linv_s[srow] = 1.0f / lrow;
    __syncthreads();

    // write O
    float* Og = g_att + ((size_t)(b * L_ + qB)) * D_ + h * HD_;
    #pragma unroll
    for (int i = 0; i < 2; i++) {
        const int r = wm * 32 + i * 16 + gid;
        const float i0 = linv_s[r], i1 = linv_s[r + 8];
        #pragma unroll
        for (int j = 0; j < 4; j++) {
            const int c = wn * 32 + j * 8 + 2 * tig;
            float2 v0 = make_float2(Oacc[i][j][0] * i0, Oacc[i][j][1] * i0);
            float2 v1 = make_float2(Oacc[i][j][2] * i1, Oacc[i][j][3] * i1);
            *(float2*)&Og[(size_t)r * D_ + c]       = v0;
            *(float2*)&Og[(size_t)(r + 8) * D_ + c] = v1;
        }
    }
}

// ---------------------------------------------------------------------------
// Launch.  Inputs: q, k, v, Wq, bq, Wk, bk, Wv, bv, Wo, bo
// ---------------------------------------------------------------------------
extern "C" void kernel_launch(void* const* d_in, const int* in_sizes, int n_in,
                              void* d_out, int out_size)
{
    (void)in_sizes; (void)n_in; (void)out_size;
    const float* q  = (const float*)d_in[0];
    const float* k  = (const float*)d_in[1];
    const float* v  = (const float*)d_in[2];
    const float* Wq = (const float*)d_in[3];
    const float* bq = (const float*)d_in[4];
    const float* Wk = (const float*)d_in[5];
    const float* bk = (const float*)d_in[6];
    const float* Wv = (const float*)d_in[7];
    const float* bv = (const float*)d_in[8];
    const float* Wo = (const float*)d_in[9];
    const float* bo = (const float*)d_in[10];
    float* out = (float*)d_out;

    float *Qp, *Kp, *Vp, *Ap;
    cudaGetSymbolAddress((void**)&Qp, g_Q);
    cudaGetSymbolAddress((void**)&Kp, g_K);
    cudaGetSymbolAddress((void**)&Vp, g_V);
    cudaGetSymbolAddress((void**)&Ap, g_att);

    cudaFuncSetAttribute(attn_tf32, cudaFuncAttributeMaxDynamicSharedMemorySize,
                         ATT_SMEM_BYTES);

    const dim3 gemmGrid(D_ / 128, M_ / 128);   // (8, 64)
    gemm_tf32<<<gemmGrid, 256>>>(q, Wq, bq, Qp);
    gemm_tf32<<<gemmGrid, 256>>>(k, Wk, bk, Kp);
    gemm_tf32<<<gemmGrid, 256>>>(v, Wv, bv, Vp);

    const dim3 attGrid(L_ / 128, H_, B_);      // (16, 16, 4)
    attn_tf32<<<attGrid, 256, ATT_SMEM_BYTES>>>(Ap);

    gemm_tf32<<<gemmGrid, 256>>>(Ap, Wo, bo, out);
}

// round 6
// speedup vs baseline: 3.7712x; 1.2351x over previous
#include <cuda_runtime.h>

// Problem constants
constexpr int B_  = 4;
constexpr int L_  = 2048;
constexpr int D_  = 1024;
constexpr int H_  = 16;
constexpr int HD_ = 64;
constexpr int M_  = B_ * L_;          // 8192 rows
constexpr float SCALE = 0.125f;       // 1/sqrt(64)

// Scratch (allocation-free rule: __device__ globals)
__device__ float g_Q[(size_t)M_ * D_];
__device__ float g_K[(size_t)M_ * D_];
__device__ float g_V[(size_t)M_ * D_];
__device__ float g_att[(size_t)M_ * D_];

// ---------------------------------------------------------------------------
// helpers
// ---------------------------------------------------------------------------
__device__ __forceinline__ float f2tf(float f) {
    unsigned u;
    asm("cvt.rna.tf32.f32 %0, %1;" : "=r"(u) : "f"(f));
    return __uint_as_float(u);
}

// D = A(16x8 row) * B(8x8 col) + D, tf32 in, fp32 accum
__device__ __forceinline__ void mma8(float* c, const unsigned* a, const unsigned* b) {
    asm volatile(
        "mma.sync.aligned.m16n8k8.row.col.f32.tf32.tf32.f32 "
        "{%0,%1,%2,%3}, {%4,%5,%6,%7}, {%8,%9}, {%0,%1,%2,%3};"
        : "+f"(c[0]), "+f"(c[1]), "+f"(c[2]), "+f"(c[3])
        : "r"(a[0]), "r"(a[1]), "r"(a[2]), "r"(a[3]), "r"(b[0]), "r"(b[1]));
}

// ldmatrix x4: each 16B "row" = 4 tf32 values; distributes one tf32/thread/matrix
__device__ __forceinline__ void ldsm4(unsigned& r0, unsigned& r1, unsigned& r2,
                                      unsigned& r3, const float* p) {
    unsigned a = (unsigned)__cvta_generic_to_shared(p);
    asm volatile("ldmatrix.sync.aligned.m8n8.x4.shared.b16 {%0,%1,%2,%3}, [%4];"
                 : "=r"(r0), "=r"(r1), "=r"(r2), "=r"(r3) : "r"(a));
}

// ---------------------------------------------------------------------------
// tf32 GEMM (NT): C[M,1024] = A[M,1024]*W[1024,1024]^T + bias
// 128x128 tile, BK=16, 256 thr, 8 warps 2(M)x4(N) -> 64x32 warp tiles.
// smem double-buffered, LDSM fragment loads, STS.128 staging. KPAD=20 is
// conflict-free for both the float4 stores and the 8-row LDSM reads.
// ---------------------------------------------------------------------------
constexpr int KPAD = 20;

__global__ __launch_bounds__(256) void gemm_tf32(
    const float* __restrict__ A, const float* __restrict__ W,
    const float* __restrict__ bias, float* __restrict__ C)
{
    __shared__ float As[2][128][KPAD];
    __shared__ float Ws[2][128][KPAD];

    const int t    = threadIdx.x;
    const int lane = t & 31;
    const int l7   = lane & 7;
    const int wid  = t >> 5;
    const int wm   = wid & 1;
    const int wn   = wid >> 1;
    const int rowB = blockIdx.y * 128;
    const int colB = blockIdx.x * 128;

    const int sr = t >> 2;            // 0..63
    const int sc = (t & 3) * 4;       // 0,4,8,12
    const float* Ag = A + (size_t)(rowB + sr) * D_ + sc;
    const float* Wg = W + (size_t)(colB + sr) * D_ + sc;

    float acc[4][4][4] = {};

    float4 pa0 = *(const float4*)Ag;
    float4 pa1 = *(const float4*)(Ag + (size_t)64 * D_);
    float4 pw0 = *(const float4*)Wg;
    float4 pw1 = *(const float4*)(Wg + (size_t)64 * D_);

#define STASH(buf)                                                             \
    do {                                                                       \
        float4 v;                                                              \
        v.x=f2tf(pa0.x); v.y=f2tf(pa0.y); v.z=f2tf(pa0.z); v.w=f2tf(pa0.w);    \
        *(float4*)&As[buf][sr][sc] = v;                                        \
        v.x=f2tf(pa1.x); v.y=f2tf(pa1.y); v.z=f2tf(pa1.z); v.w=f2tf(pa1.w);    \
        *(float4*)&As[buf][sr + 64][sc] = v;                                   \
        v.x=f2tf(pw0.x); v.y=f2tf(pw0.y); v.z=f2tf(pw0.z); v.w=f2tf(pw0.w);    \
        *(float4*)&Ws[buf][sr][sc] = v;                                        \
        v.x=f2tf(pw1.x); v.y=f2tf(pw1.y); v.z=f2tf(pw1.z); v.w=f2tf(pw1.w);    \
        *(float4*)&Ws[buf][sr + 64][sc] = v;                                   \
    } while (0)

    STASH(0);
    __syncthreads();

    for (int kt = 0; kt < 64; kt++) {
        const int cur = kt & 1;
        if (kt < 63) {
            const int ko = (kt + 1) * 16;
            pa0 = *(const float4*)(Ag + ko);
            pa1 = *(const float4*)(Ag + (size_t)64 * D_ + ko);
            pw0 = *(const float4*)(Wg + ko);
            pw1 = *(const float4*)(Wg + (size_t)64 * D_ + ko);
        }
        #pragma unroll
        for (int kc = 0; kc < 2; kc++) {
            const int kk = kc * 8;
            unsigned af[4][4], bf[4][2];
            #pragma unroll
            for (int i = 0; i < 4; i++) {
                const int m  = lane >> 3;                  // 0..3
                const int rr = wm * 64 + i * 16 + (m & 1) * 8 + l7;
                const int cc = kk + (m >> 1) * 4;
                ldsm4(af[i][0], af[i][1], af[i][2], af[i][3], &As[cur][rr][cc]);
            }
            #pragma unroll
            for (int jp = 0; jp < 2; jp++) {
                const int m  = lane >> 3;
                const int rr = wn * 32 + (jp * 2 + (m >> 1)) * 8 + l7;
                const int cc = kk + (m & 1) * 4;
                ldsm4(bf[jp*2][0], bf[jp*2][1], bf[jp*2+1][0], bf[jp*2+1][1],
                      &Ws[cur][rr][cc]);
            }
            #pragma unroll
            for (int i = 0; i < 4; i++)
                #pragma unroll
                for (int j = 0; j < 4; j++)
                    mma8(acc[i][j], af[i], bf[j]);
        }
        if (kt < 63) STASH(1 - cur);
        __syncthreads();
    }
#undef STASH

    const int gid = lane >> 2;
    const int tig = lane & 3;
    #pragma unroll
    for (int i = 0; i < 4; i++) {
        const int row = rowB + wm * 64 + i * 16 + gid;
        #pragma unroll
        for (int j = 0; j < 4; j++) {
            const int col = colB + wn * 32 + j * 8 + 2 * tig;
            const float bx = bias[col], by = bias[col + 1];
            float2 v0 = make_float2(acc[i][j][0] + bx, acc[i][j][1] + by);
            float2 v1 = make_float2(acc[i][j][2] + bx, acc[i][j][3] + by);
            *(float2*)&C[(size_t)row * D_ + col]       = v0;
            *(float2*)&C[(size_t)(row + 8) * D_ + col] = v1;
        }
    }
}

// ---------------------------------------------------------------------------
// Flash attention v2, tf32 tensor cores, register softmax.
// 128 threads = 4 warps, each owns 16 q-rows (Q-tile 64), key-tile 64.
// Q fragments in registers. S stays in registers -> shfl softmax -> P stored
// once to a warp-private swizzled strip -> ldmatrix A-frags for P.V.
// grid (L/64, H, B).
// ---------------------------------------------------------------------------
// dynamic smem word offsets
constexpr int KS_W = 0;                 // Ks[64][64] swizzled
constexpr int VS_W = 4096;              // Vs[64][72]
constexpr int PS_W = VS_W + 64 * 72;    // Ps[64][64] swizzled
constexpr int ATT_SMEM_BYTES = (PS_W + 4096) * 4;   // 51200 B

// stride-64 XOR-swizzled word index (16B-group granularity)
__device__ __forceinline__ int swz(int row, int col) {
    return row * 64 + ((((col >> 2) ^ (row & 7)) << 2) | (col & 3));
}

__global__ __launch_bounds__(128) void attn_tf32(float* __restrict__ out)
{
    extern __shared__ float sm[];
    float* Ks = sm + KS_W;
    float* Vs = sm + VS_W;
    float* Ps = sm + PS_W;

    const int t    = threadIdx.x;
    const int lane = t & 31;
    const int gid  = lane >> 2;
    const int tig  = lane & 3;
    const int l7   = lane & 7;
    const int wm   = t >> 5;            // warp id = M strip
    const int b    = blockIdx.z;
    const int h    = blockIdx.y;
    const int qB   = blockIdx.x * 64;

    // Q fragments in registers (pre-scaled, tf32-rounded)
    unsigned qa[8][4];
    {
        const float* Qg = g_Q + ((size_t)(b * L_ + qB + wm * 16)) * D_ + h * HD_;
        #pragma unroll
        for (int kc = 0; kc < 8; kc++) {
            const int k0 = kc * 8 + tig;
            qa[kc][0] = __float_as_uint(f2tf(Qg[(size_t)gid * D_ + k0]           * SCALE));
            qa[kc][1] = __float_as_uint(f2tf(Qg[(size_t)(gid + 8) * D_ + k0]     * SCALE));
            qa[kc][2] = __float_as_uint(f2tf(Qg[(size_t)gid * D_ + k0 + 4]       * SCALE));
            qa[kc][3] = __float_as_uint(f2tf(Qg[(size_t)(gid + 8) * D_ + k0 + 4] * SCALE));
        }
    }

    float o[8][4] = {};
    float m0 = -1e30f, m1 = -1e30f, l0 = 0.0f, l1 = 0.0f;
    const int rr = wm * 16 + gid;       // this thread's P/S row (and rr+8)

    for (int kt = 0; kt < L_; kt += 64) {
        const float* Kg = g_K + ((size_t)(b * L_ + kt)) * D_ + h * HD_;
        const float* Vg = g_V + ((size_t)(b * L_ + kt)) * D_ + h * HD_;
        __syncthreads();                // previous tile fully consumed
        for (int i = t; i < 64 * 16; i += 128) {
            const int r = i >> 4, c = (i & 15) * 4;
            float4 kv = *(const float4*)&Kg[(size_t)r * D_ + c];
            float4 vv = *(const float4*)&Vg[(size_t)r * D_ + c];
            float4 w;
            w.x = f2tf(kv.x); w.y = f2tf(kv.y); w.z = f2tf(kv.z); w.w = f2tf(kv.w);
            *(float4*)&Ks[swz(r, c)] = w;       // c%4==0 -> 16B aligned
            w.x = f2tf(vv.x); w.y = f2tf(vv.y); w.z = f2tf(vv.z); w.w = f2tf(vv.w);
            *(float4*)&Vs[r * 72 + c] = w;
        }
        __syncthreads();

        // ---- S = Q . K^T  (16 x 64 per warp), accum in registers
        float s[8][4] = {};
        #pragma unroll
        for (int kc = 0; kc < 8; kc++) {
            const int kk = kc * 8;
            unsigned bf[8][2];
            #pragma unroll
            for (int jp = 0; jp < 4; jp++) {
                const int m  = lane >> 3;
                const int kr = (jp * 2 + (m >> 1)) * 8 + l7;     // key row
                const int cc = kk + (m & 1) * 4;
                ldsm4(bf[jp*2][0], bf[jp*2][1], bf[jp*2+1][0], bf[jp*2+1][1],
                      &Ks[swz(kr, cc)]);
            }
            #pragma unroll
            for (int j = 0; j < 8; j++)
                mma8(s[j], qa[kc], bf[j]);
        }

        // ---- online softmax in registers (rows rr and rr+8)
        float mx0 = -1e30f, mx1 = -1e30f;
        #pragma unroll
        for (int j = 0; j < 8; j++) {
            mx0 = fmaxf(mx0, fmaxf(s[j][0], s[j][1]));
            mx1 = fmaxf(mx1, fmaxf(s[j][2], s[j][3]));
        }
        mx0 = fmaxf(mx0, __shfl_xor_sync(0xffffffffu, mx0, 1));
        mx0 = fmaxf(mx0, __shfl_xor_sync(0xffffffffu, mx0, 2));
        mx1 = fmaxf(mx1, __shfl_xor_sync(0xffffffffu, mx1, 1));
        mx1 = fmaxf(mx1, __shfl_xor_sync(0xffffffffu, mx1, 2));
        const float mn0 = fmaxf(m0, mx0), mn1 = fmaxf(m1, mx1);
        const float co0 = __expf(m0 - mn0), co1 = __expf(m1 - mn1);
        float sum0 = 0.0f, sum1 = 0.0f;
        #pragma unroll
        for (int j = 0; j < 8; j++) {
            const float p0 = __expf(s[j][0] - mn0);
            const float p1 = __expf(s[j][1] - mn0);
            const float p2 = __expf(s[j][2] - mn1);
            const float p3 = __expf(s[j][3] - mn1);
            sum0 += p0 + p1; sum1 += p2 + p3;
            const int c = j * 8 + 2 * tig;
            *(float2*)&Ps[swz(rr, c)]     = make_float2(f2tf(p0), f2tf(p1));
            *(float2*)&Ps[swz(rr + 8, c)] = make_float2(f2tf(p2), f2tf(p3));
        }
        sum0 += __shfl_xor_sync(0xffffffffu, sum0, 1);
        sum0 += __shfl_xor_sync(0xffffffffu, sum0, 2);
        sum1 += __shfl_xor_sync(0xffffffffu, sum1, 1);
        sum1 += __shfl_xor_sync(0xffffffffu, sum1, 2);
        l0 = l0 * co0 + sum0; m0 = mn0;
        l1 = l1 * co1 + sum1; m1 = mn1;

        // rescale O
        #pragma unroll
        for (int j = 0; j < 8; j++) {
            o[j][0] *= co0; o[j][1] *= co0;
            o[j][2] *= co1; o[j][3] *= co1;
        }
        __syncwarp();                   // P strip visible to whole warp

        // ---- O += P . V   (k = 64 keys)
        #pragma unroll
        for (int kc = 0; kc < 8; kc++) {
            const int kk = kc * 8;
            unsigned af[4];
            {
                const int m  = lane >> 3;
                const int pr = wm * 16 + (m & 1) * 8 + l7;
                const int cc = kk + (m >> 1) * 4;
                ldsm4(af[0], af[1], af[2], af[3], &Ps[swz(pr, cc)]);
            }
            #pragma unroll
            for (int j = 0; j < 8; j++) {
                unsigned bv[2];
                bv[0] = __float_as_uint(Vs[(kk + tig)     * 72 + j * 8 + gid]);
                bv[1] = __float_as_uint(Vs[(kk + tig + 4) * 72 + j * 8 + gid]);
                mma8(o[j], af, bv);
            }
        }
    }

    // ---- normalize + write
    const float i0 = 1.0f / l0, i1 = 1.0f / l1;
    float* Og = g_att + ((size_t)(b * L_ + qB + wm * 16)) * D_ + h * HD_;
    #pragma unroll
    for (int j = 0; j < 8; j++) {
        const int c = j * 8 + 2 * tig;
        *(float2*)&Og[(size_t)gid * D_ + c] =
            make_float2(o[j][0] * i0, o[j][1] * i0);
        *(float2*)&Og[(size_t)(gid + 8) * D_ + c] =
            make_float2(o[j][2] * i1, o[j][3] * i1);
    }
}

// ---------------------------------------------------------------------------
// Launch.  Inputs: q, k, v, Wq, bq, Wk, bk, Wv, bv, Wo, bo
// ---------------------------------------------------------------------------
extern "C" void kernel_launch(void* const* d_in, const int* in_sizes, int n_in,
                              void* d_out, int out_size)
{
    (void)in_sizes; (void)n_in; (void)out_size;
    const float* q  = (const float*)d_in[0];
    const float* k  = (const float*)d_in[1];
    const float* v  = (const float*)d_in[2];
    const float* Wq = (const float*)d_in[3];
    const float* bq = (const float*)d_in[4];
    const float* Wk = (const float*)d_in[5];
    const float* bk = (const float*)d_in[6];
    const float* Wv = (const float*)d_in[7];
    const float* bv = (const float*)d_in[8];
    const float* Wo = (const float*)d_in[9];
    const float* bo = (const float*)d_in[10];
    float* out = (float*)d_out;

    float *Qp, *Kp, *Vp, *Ap;
    cudaGetSymbolAddress((void**)&Qp, g_Q);
    cudaGetSymbolAddress((void**)&Kp, g_K);
    cudaGetSymbolAddress((void**)&Vp, g_V);
    cudaGetSymbolAddress((void**)&Ap, g_att);

    cudaFuncSetAttribute(attn_tf32, cudaFuncAttributeMaxDynamicSharedMemorySize,
                         ATT_SMEM_BYTES);

    const dim3 gemmGrid(D_ / 128, M_ / 128);   // (8, 64)
    gemm_tf32<<<gemmGrid, 256>>>(q, Wq, bq, Qp);
    gemm_tf32<<<gemmGrid, 256>>>(k, Wk, bk, Kp);
    gemm_tf32<<<gemmGrid, 256>>>(v, Wv, bv, Vp);

    const dim3 attGrid(L_ / 64, H_, B_);       // (32, 16, 4)
    attn_tf32<<<attGrid, 128, ATT_SMEM_BYTES>>>(Ap);

    gemm_tf32<<<gemmGrid, 256>>>(Ap, Wo, bo, out);
}

// round 9
// speedup vs baseline: 3.7901x; 1.0050x over previous
#include <cuda_runtime.h>

// Problem constants
constexpr int B_  = 4;
constexpr int L_  = 2048;
constexpr int D_  = 1024;
constexpr int H_  = 16;
constexpr int HD_ = 64;
constexpr int M_  = B_ * L_;          // 8192 rows
constexpr float SCALE2 = 0.125f * 1.4426950408889634f;  // 1/sqrt(64) * log2(e)

// Scratch (allocation-free rule: __device__ globals)
__device__ float g_Q[(size_t)M_ * D_];
__device__ float g_K[(size_t)M_ * D_];
__device__ float g_V[(size_t)M_ * D_];
__device__ float g_att[(size_t)M_ * D_];

// ---------------------------------------------------------------------------
// helpers
// ---------------------------------------------------------------------------
__device__ __forceinline__ float f2tf(float f) {
    unsigned u;
    asm("cvt.rna.tf32.f32 %0, %1;" : "=r"(u) : "f"(f));
    return __uint_as_float(u);
}

__device__ __forceinline__ float ex2f(float x) {
    float y;
    asm("ex2.approx.f32 %0, %1;" : "=f"(y) : "f"(x));
    return y;
}

// D = A(16x8 row) * B(8x8 col) + D, tf32 in, fp32 accum
__device__ __forceinline__ void mma8(float* c, const unsigned* a, const unsigned* b) {
    asm volatile(
        "mma.sync.aligned.m16n8k8.row.col.f32.tf32.tf32.f32 "
        "{%0,%1,%2,%3}, {%4,%5,%6,%7}, {%8,%9}, {%0,%1,%2,%3};"
        : "+f"(c[0]), "+f"(c[1]), "+f"(c[2]), "+f"(c[3])
        : "r"(a[0]), "r"(a[1]), "r"(a[2]), "r"(a[3]), "r"(b[0]), "r"(b[1]));
}

// ldmatrix x4: 16B "rows" = 4 tf32; one 32-bit word per thread per matrix
__device__ __forceinline__ void ldsm4(unsigned& r0, unsigned& r1, unsigned& r2,
                                      unsigned& r3, const float* p) {
    unsigned a = (unsigned)__cvta_generic_to_shared(p);
    asm volatile("ldmatrix.sync.aligned.m8n8.x4.shared.b16 {%0,%1,%2,%3}, [%4];"
                 : "=r"(r0), "=r"(r1), "=r"(r2), "=r"(r3) : "r"(a));
}

// ---------------------------------------------------------------------------
// tf32 GEMM body (NT): C[M,1024] = A[M,1024]*W[1024,1024]^T + bias
// 128x128 tile, BK=16, 256 thr, 8 warps 2(M)x4(N) -> 64x32 warp tiles.
// ---------------------------------------------------------------------------
constexpr int KPAD = 20;

__device__ __forceinline__ void gemm_body(
    const float* __restrict__ A, const float* __restrict__ W,
    const float* __restrict__ bias, float* __restrict__ C)
{
    __shared__ float As[2][128][KPAD];
    __shared__ float Ws[2][128][KPAD];

    const int t    = threadIdx.x;
    const int lane = t & 31;
    const int l7   = lane & 7;
    const int wid  = t >> 5;
    const int wm   = wid & 1;
    const int wn   = wid >> 1;
    const int rowB = blockIdx.y * 128;
    const int colB = blockIdx.x * 128;

    const int sr = t >> 2;            // 0..63
    const int sc = (t & 3) * 4;       // 0,4,8,12
    const float* Ag = A + (size_t)(rowB + sr) * D_ + sc;
    const float* Wg = W + (size_t)(colB + sr) * D_ + sc;

    float acc[4][4][4] = {};

    float4 pa0 = *(const float4*)Ag;
    float4 pa1 = *(const float4*)(Ag + (size_t)64 * D_);
    float4 pw0 = *(const float4*)Wg;
    float4 pw1 = *(const float4*)(Wg + (size_t)64 * D_);

#define STASH(buf)                                                             \
    do {                                                                       \
        float4 v;                                                              \
        v.x=f2tf(pa0.x); v.y=f2tf(pa0.y); v.z=f2tf(pa0.z); v.w=f2tf(pa0.w);    \
        *(float4*)&As[buf][sr][sc] = v;                                        \
        v.x=f2tf(pa1.x); v.y=f2tf(pa1.y); v.z=f2tf(pa1.z); v.w=f2tf(pa1.w);    \
        *(float4*)&As[buf][sr + 64][sc] = v;                                   \
        v.x=f2tf(pw0.x); v.y=f2tf(pw0.y); v.z=f2tf(pw0.z); v.w=f2tf(pw0.w);    \
        *(float4*)&Ws[buf][sr][sc] = v;                                        \
        v.x=f2tf(pw1.x); v.y=f2tf(pw1.y); v.z=f2tf(pw1.z); v.w=f2tf(pw1.w);    \
        *(float4*)&Ws[buf][sr + 64][sc] = v;                                   \
    } while (0)

    STASH(0);
    __syncthreads();

    for (int kt = 0; kt < 64; kt++) {
        const int cur = kt & 1;
        if (kt < 63) {
            const int ko = (kt + 1) * 16;
            pa0 = *(const float4*)(Ag + ko);
            pa1 = *(const float4*)(Ag + (size_t)64 * D_ + ko);
            pw0 = *(const float4*)(Wg + ko);
            pw1 = *(const float4*)(Wg + (size_t)64 * D_ + ko);
        }
        #pragma unroll
        for (int kc = 0; kc < 2; kc++) {
            const int kk = kc * 8;
            unsigned af[4][4], bf[4][2];
            #pragma unroll
            for (int i = 0; i < 4; i++) {
                const int m  = lane >> 3;
                const int rr = wm * 64 + i * 16 + (m & 1) * 8 + l7;
                const int cc = kk + (m >> 1) * 4;
                ldsm4(af[i][0], af[i][1], af[i][2], af[i][3], &As[cur][rr][cc]);
            }
            #pragma unroll
            for (int jp = 0; jp < 2; jp++) {
                const int m  = lane >> 3;
                const int rr = wn * 32 + (jp * 2 + (m >> 1)) * 8 + l7;
                const int cc = kk + (m & 1) * 4;
                ldsm4(bf[jp*2][0], bf[jp*2][1], bf[jp*2+1][0], bf[jp*2+1][1],
                      &Ws[cur][rr][cc]);
            }
            #pragma unroll
            for (int i = 0; i < 4; i++)
                #pragma unroll
                for (int j = 0; j < 4; j++)
                    mma8(acc[i][j], af[i], bf[j]);
        }
        if (kt < 63) STASH(1 - cur);
        __syncthreads();
    }
#undef STASH

    const int gid = lane >> 2;
    const int tig = lane & 3;
    #pragma unroll
    for (int i = 0; i < 4; i++) {
        const int row = rowB + wm * 64 + i * 16 + gid;
        #pragma unroll
        for (int j = 0; j < 4; j++) {
            const int col = colB + wn * 32 + j * 8 + 2 * tig;
            const float bx = bias[col], by = bias[col + 1];
            float2 v0 = make_float2(acc[i][j][0] + bx, acc[i][j][1] + by);
            float2 v1 = make_float2(acc[i][j][2] + bx, acc[i][j][3] + by);
            *(float2*)&C[(size_t)row * D_ + col]       = v0;
            *(float2*)&C[(size_t)(row + 8) * D_ + col] = v1;
        }
    }
}

// Fused Q/K/V projection: grid.z selects which projection this block computes.
__global__ __launch_bounds__(256) void gemm_qkv(
    const float* __restrict__ q,  const float* __restrict__ k,
    const float* __restrict__ v,
    const float* __restrict__ Wq, const float* __restrict__ bq,
    const float* __restrict__ Wk, const float* __restrict__ bk,
    const float* __restrict__ Wv, const float* __restrict__ bv)
{
    const float *A, *W, *bias;
    float* C;
    if (blockIdx.z == 0)      { A = q; W = Wq; bias = bq; C = g_Q; }
    else if (blockIdx.z == 1) { A = k; W = Wk; bias = bk; C = g_K; }
    else                      { A = v; W = Wv; bias = bv; C = g_V; }
    gemm_body(A, W, bias, C);
}

__global__ __launch_bounds__(256) void gemm_o(
    const float* __restrict__ W, const float* __restrict__ bias,
    float* __restrict__ C)
{
    gemm_body(g_att, W, bias, C);
}

// ---------------------------------------------------------------------------
// Flash attention v2, tf32, register softmax (exp2 domain), all-LDSM frags.
// 128 threads = 4 warps x 16 q-rows (Q-tile 64), key-tile 64.
// Per tile: stage K(swz)+V(linear) -> transpose V->Vt(swz) -> S=QK^T (reg)
// -> softmax (shfl) -> P to warp strip (swz) -> O += P.V (ldsm A & B frags).
// grid (L/64, H, B).
// ---------------------------------------------------------------------------
constexpr int KS_W = 0;                 // Ks[64][64] swizzled
constexpr int VS_W = 4096;              // Vs[64][64] linear
constexpr int VT_W = 8192;              // Vt[64(hd)][64(key)] swizzled
constexpr int PS_W = 12288;             // Ps[64][64] swizzled
constexpr int ATT_SMEM_BYTES = 16384 * 4;   // 64 KB

// stride-64 XOR-swizzled word index (16B-group granularity)
__device__ __forceinline__ int swz(int row, int col) {
    return row * 64 + ((((col >> 2) ^ (row & 7)) << 2) | (col & 3));
}

__global__ __launch_bounds__(128, 3) void attn_tf32()
{
    extern __shared__ float sm[];
    float* Ks = sm + KS_W;
    float* Vs = sm + VS_W;
    float* Vt = sm + VT_W;
    float* Ps = sm + PS_W;

    const int t    = threadIdx.x;
    const int lane = t & 31;
    const int gid  = lane >> 2;
    const int tig  = lane & 3;
    const int l7   = lane & 7;
    const int wm   = t >> 5;            // warp id = M strip
    const int b    = blockIdx.z;
    const int h    = blockIdx.y;
    const int qB   = blockIdx.x * 64;

    // Q fragments in registers (pre-scaled by SCALE*log2e, tf32-rounded)
    unsigned qa[8][4];
    {
        const float* Qg = g_Q + ((size_t)(b * L_ + qB + wm * 16)) * D_ + h * HD_;
        #pragma unroll
        for (int kc = 0; kc < 8; kc++) {
            const int k0 = kc * 8 + tig;
            qa[kc][0] = __float_as_uint(f2tf(Qg[(size_t)gid * D_ + k0]           * SCALE2));
            qa[kc][1] = __float_as_uint(f2tf(Qg[(size_t)(gid + 8) * D_ + k0]     * SCALE2));
            qa[kc][2] = __float_as_uint(f2tf(Qg[(size_t)gid * D_ + k0 + 4]       * SCALE2));
            qa[kc][3] = __float_as_uint(f2tf(Qg[(size_t)(gid + 8) * D_ + k0 + 4] * SCALE2));
        }
    }

    float o[8][4] = {};
    float m0 = -1e30f, m1 = -1e30f, l0 = 0.0f, l1 = 0.0f;
    const int rr  = wm * 16 + gid;      // this thread's P/S row (and rr+8)
    const int thd = t & 63;             // transpose: hd owned by this thread
    const int tkg = (t >> 6) * 32;      // transpose: key group base

    for (int kt = 0; kt < L_; kt += 64) {
        const float* Kg = g_K + ((size_t)(b * L_ + kt)) * D_ + h * HD_;
        const float* Vg = g_V + ((size_t)(b * L_ + kt)) * D_ + h * HD_;
        __syncthreads();                // previous tile fully consumed
        for (int i = t; i < 64 * 16; i += 128) {
            const int r = i >> 4, c = (i & 15) * 4;
            float4 kv = *(const float4*)&Kg[(size_t)r * D_ + c];
            float4 vv = *(const float4*)&Vg[(size_t)r * D_ + c];
            float4 w;
            w.x = f2tf(kv.x); w.y = f2tf(kv.y); w.z = f2tf(kv.z); w.w = f2tf(kv.w);
            *(float4*)&Ks[swz(r, c)] = w;
            w.x = f2tf(vv.x); w.y = f2tf(vv.y); w.z = f2tf(vv.z); w.w = f2tf(vv.w);
            *(float4*)&Vs[r * 64 + c] = w;
        }
        __syncthreads();

        // ---- transpose Vs[key][hd] -> Vt[hd][key] (swizzled)
        #pragma unroll
        for (int kk8 = 0; kk8 < 8; kk8++) {
            const int k0 = tkg + kk8 * 4;
            float4 w;
            w.x = Vs[(k0 + 0) * 64 + thd];
            w.y = Vs[(k0 + 1) * 64 + thd];
            w.z = Vs[(k0 + 2) * 64 + thd];
            w.w = Vs[(k0 + 3) * 64 + thd];
            *(float4*)&Vt[swz(thd, k0)] = w;
        }
        __syncthreads();

        // ---- S = Q . K^T  (16 x 64 per warp), accum in registers
        float s[8][4] = {};
        #pragma unroll
        for (int kc = 0; kc < 8; kc++) {
            const int kk = kc * 8;
            unsigned bf[8][2];
            #pragma unroll
            for (int jp = 0; jp < 4; jp++) {
                const int m  = lane >> 3;
                const int kr = (jp * 2 + (m >> 1)) * 8 + l7;
                const int cc = kk + (m & 1) * 4;
                ldsm4(bf[jp*2][0], bf[jp*2][1], bf[jp*2+1][0], bf[jp*2+1][1],
                      &Ks[swz(kr, cc)]);
            }
            #pragma unroll
            for (int j = 0; j < 8; j++)
                mma8(s[j], qa[kc], bf[j]);
        }

        // ---- online softmax in registers (exp2 domain), rows rr and rr+8
        float mx0 = -1e30f, mx1 = -1e30f;
        #pragma unroll
        for (int j = 0; j < 8; j++) {
            mx0 = fmaxf(mx0, fmaxf(s[j][0], s[j][1]));
            mx1 = fmaxf(mx1, fmaxf(s[j][2], s[j][3]));
        }
        mx0 = fmaxf(mx0, __shfl_xor_sync(0xffffffffu, mx0, 1));
        mx0 = fmaxf(mx0, __shfl_xor_sync(0xffffffffu, mx0, 2));
        mx1 = fmaxf(mx1, __shfl_xor_sync(0xffffffffu, mx1, 1));
        mx1 = fmaxf(mx1, __shfl_xor_sync(0xffffffffu, mx1, 2));
        const float mn0 = fmaxf(m0, mx0), mn1 = fmaxf(m1, mx1);
        const float co0 = ex2f(m0 - mn0), co1 = ex2f(m1 - mn1);
        float sum0 = 0.0f, sum1 = 0.0f;
        #pragma unroll
        for (int j = 0; j < 8; j++) {
            const float p0 = ex2f(s[j][0] - mn0);
            const float p1 = ex2f(s[j][1] - mn0);
            const float p2 = ex2f(s[j][2] - mn1);
            const float p3 = ex2f(s[j][3] - mn1);
            sum0 += p0 + p1; sum1 += p2 + p3;
            const int c = j * 8 + 2 * tig;
            *(float2*)&Ps[swz(rr, c)]     = make_float2(f2tf(p0), f2tf(p1));
            *(float2*)&Ps[swz(rr + 8, c)] = make_float2(f2tf(p2), f2tf(p3));
        }
        sum0 += __shfl_xor_sync(0xffffffffu, sum0, 1);
        sum0 += __shfl_xor_sync(0xffffffffu, sum0, 2);
        sum1 += __shfl_xor_sync(0xffffffffu, sum1, 1);
        sum1 += __shfl_xor_sync(0xffffffffu, sum1, 2);
        l0 = l0 * co0 + sum0; m0 = mn0;
        l1 = l1 * co1 + sum1; m1 = mn1;

        // rescale O
        #pragma unroll
        for (int j = 0; j < 8; j++) {
            o[j][0] *= co0; o[j][1] *= co0;
            o[j][2] *= co1; o[j][3] *= co1;
        }
        __syncwarp();                   // P strip visible to whole warp

        // ---- O += P . V   (k = 64 keys), all fragments via ldmatrix
        #pragma unroll
        for (int kc = 0; kc < 8; kc++) {
            const int kk = kc * 8;
            unsigned af[4];
            {
                const int m  = lane >> 3;
                const int pr = wm * 16 + (m & 1) * 8 + l7;
                const int cc = kk + (m >> 1) * 4;
                ldsm4(af[0], af[1], af[2], af[3], &Ps[swz(pr, cc)]);
            }
            unsigned bf[8][2];
            #pragma unroll
            for (int jp = 0; jp < 4; jp++) {
                const int m  = lane >> 3;
                const int vr = (jp * 2 + (m >> 1)) * 8 + l7;   // hd row of Vt
                const int cc = kk + (m & 1) * 4;
                ldsm4(bf[jp*2][0], bf[jp*2][1], bf[jp*2+1][0], bf[jp*2+1][1],
                      &Vt[swz(vr, cc)]);
            }
            #pragma unroll
            for (int j = 0; j < 8; j++)
                mma8(o[j], af, bf[j]);
        }
    }

    // ---- normalize + write
    const float i0 = 1.0f / l0, i1 = 1.0f / l1;
    float* Og = g_att + ((size_t)(b * L_ + qB + wm * 16)) * D_ + h * HD_;
    #pragma unroll
    for (int j = 0; j < 8; j++) {
        const int c = j * 8 + 2 * tig;
        *(float2*)&Og[(size_t)gid * D_ + c] =
            make_float2(o[j][0] * i0, o[j][1] * i0);
        *(float2*)&Og[(size_t)(gid + 8) * D_ + c] =
            make_float2(o[j][2] * i1, o[j][3] * i1);
    }
}

// ---------------------------------------------------------------------------
// Launch.  Inputs: q, k, v, Wq, bq, Wk, bk, Wv, bv, Wo, bo
// ---------------------------------------------------------------------------
extern "C" void kernel_launch(void* const* d_in, const int* in_sizes, int n_in,
                              void* d_out, int out_size)
{
    (void)in_sizes; (void)n_in; (void)out_size;
    const float* q  = (const float*)d_in[0];
    const float* k  = (const float*)d_in[1];
    const float* v  = (const float*)d_in[2];
    const float* Wq = (const float*)d_in[3];
    const float* bq = (const float*)d_in[4];
    const float* Wk = (const float*)d_in[5];
    const float* bk = (const float*)d_in[6];
    const float* Wv = (const float*)d_in[7];
    const float* bv = (const float*)d_in[8];
    const float* Wo = (const float*)d_in[9];
    const float* bo = (const float*)d_in[10];
    float* out = (float*)d_out;

    cudaFuncSetAttribute(attn_tf32, cudaFuncAttributeMaxDynamicSharedMemorySize,
                         ATT_SMEM_BYTES);

    const dim3 qkvGrid(D_ / 128, M_ / 128, 3);   // (8, 64, 3)
    gemm_qkv<<<qkvGrid, 256>>>(q, k, v, Wq, bq, Wk, bk, Wv, bv);

    const dim3 attGrid(L_ / 64, H_, B_);         // (32, 16, 4)
    attn_tf32<<<attGrid, 128, ATT_SMEM_BYTES>>>();

    const dim3 oGrid(D_ / 128, M_ / 128);        // (8, 64)
    gemm_o<<<oGrid, 256>>>(Wo, bo, out);
}